// round 3
// baseline (speedup 1.0000x reference)
#include <cuda_runtime.h>
#include <cstdint>

// Problem constants (fixed-shape problem):
//   grad_last: (B=8, M=4096) float32
//   indices:   (M=4096,) int32 (JAX int64 request is silently int32 w/o x64),
//              values in [0, N=2048)
//   out:       (8, 4096, 2048) float32  -> 67,108,864 elements = 256 MB
//
// out[b, i, j] = (j == indices[i]) ? grad_last[b, i] : 0
//
// One thread per float4 (4 output elements). 512 float4 per (b,i) row.
// Total float4 = 8 * 4096 * 512 = 16,777,216 = 65536 blocks * 256 threads.

static constexpr unsigned B_DIM = 8;
static constexpr unsigned M_DIM = 4096;
static constexpr unsigned N_DIM = 2048;
static constexpr unsigned VEC_PER_ROW = N_DIM / 4;          // 512
static constexpr unsigned TOTAL_VEC = B_DIM * M_DIM * VEC_PER_ROW; // 16,777,216

__global__ void __launch_bounds__(256)
reduce_max_grad_scatter(const float* __restrict__ grad_last,
                        const int* __restrict__ indices,
                        float4* __restrict__ out)
{
    unsigned t = blockIdx.x * 256u + threadIdx.x;   // exact grid, no guard needed
    unsigned row = t >> 9;            // (b*4096 + i), 512 float4 per row
    unsigned q   = t & 511u;          // which float4 within the row
    unsigned i   = row & (M_DIM - 1u);

    // indices[i] is uniform for 512 consecutive threads -> broadcast L1 hit
    unsigned ind = (unsigned)__ldg(&indices[i]);

    float4 v = make_float4(0.f, 0.f, 0.f, 0.f);
    if ((ind >> 2) == q) {
        unsigned b = row >> 12;       // row / 4096
        float g = __ldg(&grad_last[b * M_DIM + i]);
        unsigned lane = ind & 3u;
        v.x = (lane == 0u) ? g : 0.f;
        v.y = (lane == 1u) ? g : 0.f;
        v.z = (lane == 2u) ? g : 0.f;
        v.w = (lane == 3u) ? g : 0.f;
    }
    out[t] = v;
}

extern "C" void kernel_launch(void* const* d_in, const int* in_sizes, int n_in,
                              void* d_out, int out_size)
{
    const float* grad    = (const float*)d_in[0];
    const int*   indices = (const int*)d_in[1];
    float4*      out     = (float4*)d_out;

    (void)in_sizes; (void)n_in; (void)out_size;

    reduce_max_grad_scatter<<<TOTAL_VEC / 256, 256>>>(grad, indices, out);
}

// round 4
// speedup vs baseline: 1.0150x; 1.0150x over previous
#include <cuda_runtime.h>
#include <cstdint>
#include <cstddef>

// Problem constants (fixed-shape problem):
//   grad_last: (B=8, M=4096) float32
//   indices:   (M=4096,) int32, values in [0, N=2048)
//   out:       (8, 4096, 2048) float32  -> 256 MB
//
// out[b, i, j] = (j == indices[i]) ? grad_last[b, i] : 0
//
// One block (128 threads) per output row (2048 floats = 512 float4).
// Each thread writes 4 float4 (64 B), batched back-to-back for write MLP.
// Store j of the block covers a contiguous 2 KB slab -> perfectly coalesced,
// full 32B sectors. Streaming store hint (.cs): output has zero reuse.

static constexpr unsigned B_DIM = 8;
static constexpr unsigned M_DIM = 4096;
static constexpr unsigned ROWS  = B_DIM * M_DIM;            // 32768 blocks
static constexpr unsigned VEC_PER_ROW = 512;                // 2048 / 4

__global__ void __launch_bounds__(128)
reduce_max_grad_scatter(const float* __restrict__ grad_last,
                        const int* __restrict__ indices,
                        float4* __restrict__ out)
{
    const unsigned row = blockIdx.x;          // b*4096 + i
    const unsigned i   = row & (M_DIM - 1u);
    const unsigned b   = row >> 12;
    const unsigned tid = threadIdx.x;

    // Both loads are block-uniform -> L1 broadcast hits.
    const unsigned ind = (unsigned)__ldg(&indices[i]);
    const float    g   = __ldg(&grad_last[b * M_DIM + i]);

    const unsigned target = ind >> 2;         // which float4 holds the hot lane
    const unsigned lane   = ind & 3u;

    float4* o = out + (size_t)row * VEC_PER_ROW + tid;

#pragma unroll
    for (int j = 0; j < 4; j++) {
        const unsigned q = j * 128u + tid;
        float4 v = make_float4(0.f, 0.f, 0.f, 0.f);
        if (q == target) {                    // taken by exactly 1 of 512 (thread,j)
            v.x = (lane == 0u) ? g : 0.f;
            v.y = (lane == 1u) ? g : 0.f;
            v.z = (lane == 2u) ? g : 0.f;
            v.w = (lane == 3u) ? g : 0.f;
        }
        __stcs(&o[j * 128], v);               // streaming store, evict-first
    }
}

extern "C" void kernel_launch(void* const* d_in, const int* in_sizes, int n_in,
                              void* d_out, int out_size)
{
    const float* grad    = (const float*)d_in[0];
    const int*   indices = (const int*)d_in[1];
    float4*      out     = (float4*)d_out;

    (void)in_sizes; (void)n_in; (void)out_size;

    reduce_max_grad_scatter<<<ROWS, 128>>>(grad, indices, out);
}